// round 3
// baseline (speedup 1.0000x reference)
#include <cuda_runtime.h>

// Shapes: B=32, N=128, IN_CH=16, IN_DIM=32, OUT_CH=32, OUT_DIM=32, P=N*IN_CH=2048
// x[b,n,c,i]  : b*65536 + n*512 + c*32 + i
// W[c,o,i,j]  : c*32768 + o*1024 + i*32 + j
// b_ij[b,p,o] : b*65536 + p*32 + o        (p = n*16 + c)
// y/z[b,o,c,i]: (b*32+o)*512 + c*32 + i

__device__ float g_b [32*2048*32];   // routing logits (8 MB)
__device__ float g_y [32*32*16*32];  // weighted-x contraction (2 MB)
__device__ float g_y0[32*16*32];     // iter-0 (uniform weights) version, o-independent
__device__ float g_z [32*32*16*32];  // W·v contraction (2 MB)
__device__ float g_t [32*32];        // per-(b,o) logsumexp offset: weight = exp(b - t)

// ---------------------------------------------------------------------------
// k_y0: y0[b,c,i] = (1/2048) * sum_n x[b,n,c,i].   grid 32 (b), 512 threads.
// ---------------------------------------------------------------------------
__global__ void k_y0(const float* __restrict__ x)
{
    int b = blockIdx.x, t = threadIdx.x;          // t = c*32 + i  (exactly 512 slots)
    const float* xb = x + b*65536 + t;
    float acc = 0.f;
    #pragma unroll 8
    for (int n = 0; n < 128; ++n) acc += xb[n*512];
    g_y0[b*512 + t] = acc * (1.f/2048.f);
}

// ---------------------------------------------------------------------------
// k_stats: per (b,o): t = max_p b + ln(sum_p exp(b - max)).  grid 32 (b), 1024 thr.
// ---------------------------------------------------------------------------
__global__ void k_stats()
{
    __shared__ float red[32*33];
    int b = blockIdx.x;
    int t = threadIdx.x, lane = t & 31, w = t >> 5;    // 32 warps, lane = o
    const float* bb = g_b + b*65536 + lane;
    float m = -1e30f;
    for (int p = w; p < 2048; p += 32)
        m = fmaxf(m, bb[p*32]);
    red[w*33 + lane] = m;
    __syncthreads();
    for (int s2 = 16; s2; s2 >>= 1) {
        if (w < s2) red[w*33+lane] = fmaxf(red[w*33+lane], red[(w+s2)*33+lane]);
        __syncthreads();
    }
    m = red[lane];
    __syncthreads();
    float s = 0.f;
    for (int p = w; p < 2048; p += 32)
        s += __expf(bb[p*32] - m);
    red[w*33 + lane] = s;
    __syncthreads();
    for (int s2 = 16; s2; s2 >>= 1) {
        if (w < s2) red[w*33+lane] += red[(w+s2)*33+lane];
        __syncthreads();
    }
    if (t < 32) g_t[b*32 + t] = m + logf(red[t]);
}

// ---------------------------------------------------------------------------
// k_y: y[b,o,c,i] = sum_n exp(b_ij[b,nc,o]-t[b,o]) * x[b,n,c,i]
// grid 512 (b*16+c), 256 threads.  32x32x128 GEMM per block from smem.
// ---------------------------------------------------------------------------
__global__ void k_y(const float* __restrict__ x)
{
    __shared__ float x_sm[128*32];      // [n][i]
    __shared__ float w_sm[128*36];      // [n][o], padded
    int b = blockIdx.x >> 4, c = blockIdx.x & 15;
    int t = threadIdx.x, lane = t & 31, grp = t >> 5;   // 8 groups
    const float* xb = x + b*65536 + c*32;
    float tv = g_t[b*32 + lane];                        // lane = o for weight pass
    const float* bb = g_b + b*65536 + c*32;
    #pragma unroll
    for (int nn = 0; nn < 16; ++nn) {
        int n = nn*8 + grp;
        x_sm[n*32 + lane] = xb[n*512 + lane];
        w_sm[n*36 + lane] = __expf(bb[n*512 + lane] - tv);
    }
    __syncthreads();
    // thread: i = lane, o = grp*4 + k
    float a0=0.f, a1=0.f, a2=0.f, a3=0.f;
    int o0 = grp*4;
    #pragma unroll 4
    for (int n = 0; n < 128; ++n) {
        float xv = x_sm[n*32 + lane];
        float4 wv = *(const float4*)(w_sm + n*36 + o0);  // broadcast, aligned
        a0 += wv.x*xv; a1 += wv.y*xv; a2 += wv.z*xv; a3 += wv.w*xv;
    }
    float* yb = g_y + b*16384 + c*32 + lane;
    yb[(o0+0)*512] = a0; yb[(o0+1)*512] = a1;
    yb[(o0+2)*512] = a2; yb[(o0+3)*512] = a3;
}

// ---------------------------------------------------------------------------
// k_s: s[b,o,j] = sum_{ci} y[b,o,ci] * W[ci,o,j]; squash -> v,a;
//      z[b,o,ci] = sum_j W[ci,o,j] * v[b,o,j]
// grid 128 (o in [0,32), b-group of 8), 256 threads, 91 KB dynamic smem.
// ---------------------------------------------------------------------------
#define SMEM_S ((512*36 + 8*512 + 8*32)*4)
__global__ void k_s(const float* __restrict__ Wg, int use_y0, int write_z,
                    float* __restrict__ out)
{
    extern __shared__ float sm[];
    float* W_sm = sm;                    // [512][36] : [ci][j] padded
    float* y_sm = sm + 512*36;           // [8][512]
    float* v_sm = y_sm + 8*512;          // [8][32]
    int o  = blockIdx.x & 31;
    int b0 = (blockIdx.x >> 5) * 8;
    int t  = threadIdx.x;

    // Load W slice for this o: 16 chunks of 1024 contiguous floats
    const float4* W4 = (const float4*)Wg;
    #pragma unroll
    for (int c = 0; c < 16; ++c) {
        float4 v4 = W4[c*8192 + o*256 + t];
        int row = c*32 + (t >> 3);
        int j0  = (t & 7) * 4;
        *(float4*)(W_sm + row*36 + j0) = v4;
    }
    // Load y for 8 b's
    const float* ybase = use_y0 ? g_y0 : g_y;
    int ystride_b = use_y0 ? 512 : 16384;
    int ystride_o = use_y0 ? 0   : 512;
    #pragma unroll
    for (int q = 0; q < 16; ++q) {
        int idx = q*256 + t;
        int bb = idx >> 9, ci = idx & 511;
        y_sm[bb*512 + ci] = ybase[(b0+bb)*ystride_b + o*ystride_o + ci];
    }
    __syncthreads();

    int bb = t >> 5, j = t & 31;            // warp = local b, lane = j
    const float4* y4 = (const float4*)(y_sm + bb*512);
    float acc = 0.f;
    #pragma unroll 4
    for (int c4 = 0; c4 < 128; ++c4) {
        float4 yv = y4[c4];
        int ci = c4*4;
        acc += yv.x*W_sm[(ci  )*36+j] + yv.y*W_sm[(ci+1)*36+j]
             + yv.z*W_sm[(ci+2)*36+j] + yv.w*W_sm[(ci+3)*36+j];
    }
    // squash along j
    float mag_sq = acc*acc;
    #pragma unroll
    for (int s2 = 16; s2; s2 >>= 1) mag_sq += __shfl_xor_sync(0xffffffffu, mag_sq, s2);
    float mag = sqrtf(mag_sq) + 1e-11f;
    float a   = mag_sq / (1.f + mag_sq);
    float v   = acc * (a / mag);
    v_sm[bb*32 + j] = v;
    int b = b0 + bb;
    if (out) {
        out[(b*32 + o)*32 + j] = v;
        if (j == 0) out[32768 + b*32 + o] = a;
    }
    if (write_z) {
        __syncthreads();
        float4 vq[8];
        const float4* vv4 = (const float4*)(v_sm + bb*32);
        #pragma unroll
        for (int q = 0; q < 8; ++q) vq[q] = vv4[q];
        float* zb = g_z + (b*32 + o)*512;
        #pragma unroll
        for (int k = 0; k < 16; ++k) {
            int ci = j + k*32;
            const float4* wr = (const float4*)(W_sm + ci*36);
            float za = 0.f;
            #pragma unroll
            for (int q = 0; q < 8; ++q) {
                float4 w4 = wr[q];
                za += w4.x*vq[q].x + w4.y*vq[q].y + w4.z*vq[q].z + w4.w*vq[q].w;
            }
            zb[ci] = za;
        }
    }
}

// ---------------------------------------------------------------------------
// k_upd: b_ij[b, n*16+c, o] (+)= sum_i x[b,n,c,i] * z[b,o,c,i]
// grid 512 (b*16+c), 256 threads.  128x32x32 GEMM per block.
// ---------------------------------------------------------------------------
__global__ void k_upd(const float* __restrict__ x, int first)
{
    __shared__ float x_sm[128*32];   // [n][i]
    __shared__ float z_sm[32*36];    // [o][i] padded
    int b = blockIdx.x >> 4, c = blockIdx.x & 15;
    int t = threadIdx.x, lane = t & 31, grp = t >> 5;
    const float* xb = x + b*65536 + c*32;
    #pragma unroll
    for (int nn = 0; nn < 16; ++nn) {
        int n = nn*8 + grp;
        x_sm[n*32 + lane] = xb[n*512 + lane];
    }
    const float* zb = g_z + b*16384 + c*32;
    #pragma unroll
    for (int k = 0; k < 4; ++k) {
        int oo = k*8 + grp;
        z_sm[oo*36 + lane] = zb[oo*512 + lane];
    }
    __syncthreads();
    float* bbase = g_b + b*65536 + c*32;   // + n*512 + o
    const float4* zr = (const float4*)(z_sm + lane*36);  // lane = o
    #pragma unroll 2
    for (int nn = 0; nn < 16; ++nn) {
        int n = grp*16 + nn;
        const float4* xr = (const float4*)(x_sm + n*32);
        float acc = 0.f;
        #pragma unroll
        for (int q = 0; q < 8; ++q) {
            float4 xv = xr[q]; float4 zv = zr[q];
            acc += xv.x*zv.x + xv.y*zv.y + xv.z*zv.z + xv.w*zv.w;
        }
        float* dst = bbase + n*512 + lane;
        if (first) *dst = acc; else *dst += acc;
    }
}

// ---------------------------------------------------------------------------
extern "C" void kernel_launch(void* const* d_in, const int* in_sizes, int n_in,
                              void* d_out, int out_size)
{
    const float* x = (const float*)d_in[0];
    const float* W = (const float*)(n_in > 1 ? d_in[1] : d_in[0]);
    for (int i = 0; i < n_in; ++i) {            // robust to input ordering
        if (in_sizes[i] == 32*128*16*32)      x = (const float*)d_in[i];
        else if (in_sizes[i] == 16*32*32*32)  W = (const float*)d_in[i];
    }
    float* out = (float*)d_out;

    cudaFuncSetAttribute(k_s, cudaFuncAttributeMaxDynamicSharedMemorySize, SMEM_S);

    // iter 0: uniform softmax (1/2048)
    k_y0 <<< 32, 512 >>>(x);
    k_s  <<<128, 256, SMEM_S>>>(W, /*use_y0=*/1, /*write_z=*/1, nullptr);
    k_upd<<<512, 256>>>(x, /*first=*/1);
    // iter 1
    k_stats<<< 32,1024>>>();
    k_y  <<<512, 256>>>(x);
    k_s  <<<128, 256, SMEM_S>>>(W, 0, 1, nullptr);
    k_upd<<<512, 256>>>(x, 0);
    // iter 2 (final): write v and a, skip z / update
    k_stats<<< 32,1024>>>();
    k_y  <<<512, 256>>>(x);
    k_s  <<<128, 256, SMEM_S>>>(W, 0, 0, out);
}

// round 6
// speedup vs baseline: 1.2113x; 1.2113x over previous
#include <cuda_runtime.h>

// Shapes: B=32, N=128, IN_CH=16, IN_DIM=32, OUT_CH=32, OUT_DIM=32, P=2048
// x[b,n,c,i]  : b*65536 + n*512 + c*32 + i
// W[c,o,i,j]  : c*32768 + o*1024 + i*32 + j
// y/z[b,o,c,i]: (b*32+o)*512 + c*32 + i
//
// Routing identity: b_t = u · (z_0 + ... + z_{t-1})  (b is linear in z-history),
// so b_ij is never materialized; k_f recomputes it from x·z_cum each iteration.

__device__ float g_y  [32*32*16*32]; // unnormalized y[b,o,c,i] (2 MB)
__device__ float g_y0p[32*8*512];    // iter-0 partial means [b][k=8][ci]
__device__ float g_z  [32*32*16*32]; // cumulative z (2 MB)
__device__ float g_sp [32*16*32];    // partial weight sums [b][c][o]
__device__ float g_mp [32*16*32];    // partial b-max       [b][c][o]
__device__ float g_t  [32*32];       // softmax offset per (b,o)

// ---------------------------------------------------------------------------
// k_y0: partial uniform-softmax contraction. grid 256 (b*8+k), 512 threads.
// y0p[b,k,ci] = (1/2048) * sum_{n in chunk k} x[b,n,ci]
// ---------------------------------------------------------------------------
__global__ void k_y0(const float* __restrict__ x)
{
    int b = blockIdx.x >> 3, k = blockIdx.x & 7, t = threadIdx.x;
    const float* xb = x + b*65536 + k*16*512 + t;
    float acc = 0.f;
    #pragma unroll
    for (int n = 0; n < 16; ++n) acc += xb[n*512];
    g_y0p[b*4096 + k*512 + t] = acc * (1.f/2048.f);
}

// ---------------------------------------------------------------------------
// k_f: fused routing step for one (b,c) tile. grid 512, 256 threads.
//   phase1: du[n,o] = x[n,:]·z_cum[o,:]  (b_ij value), w = exp(du - toff[o]),
//           per-(c,o) partial max(du) and sum(w)
//   phase2: y[o,i] = sum_n w[n,o] x[n,i]  (unnormalized)
// ---------------------------------------------------------------------------
__global__ void k_f(const float* __restrict__ x, int use_toff, int write_mp)
{
    __shared__ float x_sm[128*32];   // [n][i]
    __shared__ float w_sm[128*36];   // [n][o] padded
    __shared__ float mred[8*33];
    __shared__ float sred[8*33];
    __shared__ float toff_sm[32];
    int b = blockIdx.x >> 4, c = blockIdx.x & 15;
    int t = threadIdx.x, lane = t & 31, grp = t >> 5;

    const float* xb = x + b*65536 + c*32;
    #pragma unroll
    for (int nn = 0; nn < 16; ++nn) {
        int n = nn*8 + grp;
        x_sm[n*32 + lane] = xb[n*512 + lane];
    }
    if (t < 32) toff_sm[t] = use_toff ? g_t[b*32 + t] : 0.f;

    // z_cum row for o = lane, kept in registers (conflict-free)
    float4 zr[8];
    const float4* zg = (const float4*)(g_z + (b*32 + lane)*512 + c*32);
    #pragma unroll
    for (int q = 0; q < 8; ++q) zr[q] = zg[q];
    __syncthreads();

    float toff = toff_sm[lane];
    float bmax = -1e30f, ssum = 0.f;
    #pragma unroll 2
    for (int nn = 0; nn < 16; ++nn) {
        int n = grp*16 + nn;
        const float4* xr = (const float4*)(x_sm + n*32);   // broadcast reads
        float du = 0.f;
        #pragma unroll
        for (int q = 0; q < 8; ++q) {
            float4 xv = xr[q];
            du += xv.x*zr[q].x + xv.y*zr[q].y + xv.z*zr[q].z + xv.w*zr[q].w;
        }
        bmax = fmaxf(bmax, du);
        float w = __expf(du - toff);
        ssum += w;
        w_sm[n*36 + lane] = w;                              // stride-1: no conflict
    }
    mred[grp*33 + lane] = bmax;
    sred[grp*33 + lane] = ssum;
    __syncthreads();
    if (t < 32) {
        float m = -1e30f, s = 0.f;
        #pragma unroll
        for (int g = 0; g < 8; ++g) {
            m = fmaxf(m, mred[g*33 + t]);
            s += sred[g*33 + t];
        }
        if (write_mp) g_mp[b*512 + c*32 + t] = m;
        g_sp[b*512 + c*32 + t] = s;
    }

    // phase2: thread (i=lane, o=grp*4+k)
    float a0=0.f, a1=0.f, a2=0.f, a3=0.f;
    int o0 = grp*4;
    #pragma unroll 4
    for (int n = 0; n < 128; ++n) {
        float xv = x_sm[n*32 + lane];
        float4 wv = *(const float4*)(w_sm + n*36 + o0);     // broadcast, aligned
        a0 += wv.x*xv; a1 += wv.y*xv; a2 += wv.z*xv; a3 += wv.w*xv;
    }
    float* yb = g_y + b*16384 + c*32 + lane;
    yb[(o0+0)*512] = a0; yb[(o0+1)*512] = a1;
    yb[(o0+2)*512] = a2; yb[(o0+3)*512] = a3;
}

// ---------------------------------------------------------------------------
// k_s: s[b,o,j] = (1/S) sum_ci y[b,o,ci] W[ci,o,j]; squash -> v,a;
//      z_cum[b,o,ci] (+)= sum_j W[ci,o,j] v[b,o,j]
// mode 0: y from y0p (pre-normalized), z overwrite
// mode 1: normalize by S, z accumulate, emit g_t = max_c g_mp
// mode 2: normalize by S, write v/a to out, no z
// grid 128 (o | b-group of 8), 256 threads, dyn smem.
// ---------------------------------------------------------------------------
#define SMEM_S ((512*36 + 8*512 + 8*32)*4)
__global__ void k_s(const float* __restrict__ Wg, int mode, float* __restrict__ out)
{
    extern __shared__ float sm[];
    float* W_sm = sm;                 // [512][36] : [ci][j]
    float* y_sm = sm + 512*36;        // [8][512]
    float* v_sm = y_sm + 8*512;       // [8][32]
    int o  = blockIdx.x & 31;
    int b0 = (blockIdx.x >> 5) * 8;
    int t  = threadIdx.x;

    const float4* W4 = (const float4*)Wg;
    #pragma unroll
    for (int c = 0; c < 16; ++c) {
        float4 v4 = W4[c*8192 + o*256 + t];
        int row = c*32 + (t >> 3);
        int j0  = (t & 7) * 4;
        *(float4*)(W_sm + row*36 + j0) = v4;
    }
    if (mode == 0) {
        #pragma unroll
        for (int q = 0; q < 16; ++q) {
            int idx = q*256 + t, bb = idx >> 9, ci = idx & 511;
            float acc = 0.f;
            #pragma unroll
            for (int k = 0; k < 8; ++k)
                acc += g_y0p[(b0+bb)*4096 + k*512 + ci];
            y_sm[bb*512 + ci] = acc;
        }
    } else {
        #pragma unroll
        for (int q = 0; q < 16; ++q) {
            int idx = q*256 + t, bb = idx >> 9, ci = idx & 511;
            y_sm[bb*512 + ci] = g_y[(b0+bb)*16384 + o*512 + ci];
        }
    }
    __syncthreads();

    int bb = t >> 5, j = t & 31, b = b0 + bb;

    float Sinv = 1.f;
    if (mode != 0) {
        float sv = (j < 16) ? g_sp[b*512 + j*32 + o] : 0.f;
        #pragma unroll
        for (int s2 = 16; s2; s2 >>= 1) sv += __shfl_xor_sync(0xffffffffu, sv, s2);
        Sinv = 1.f / sv;
        if (mode == 1) {
            float mv = (j < 16) ? g_mp[b*512 + j*32 + o] : -1e30f;
            #pragma unroll
            for (int s2 = 16; s2; s2 >>= 1)
                mv = fmaxf(mv, __shfl_xor_sync(0xffffffffu, mv, s2));
            if (j == 0) g_t[b*32 + o] = mv;
        }
    }

    const float4* y4 = (const float4*)(y_sm + bb*512);
    float acc = 0.f;
    #pragma unroll 4
    for (int c4 = 0; c4 < 128; ++c4) {
        float4 yv = y4[c4];
        int ci = c4*4;
        acc += yv.x*W_sm[(ci  )*36+j] + yv.y*W_sm[(ci+1)*36+j]
             + yv.z*W_sm[(ci+2)*36+j] + yv.w*W_sm[(ci+3)*36+j];
    }
    acc *= Sinv;

    float mag_sq = acc*acc;
    #pragma unroll
    for (int s2 = 16; s2; s2 >>= 1) mag_sq += __shfl_xor_sync(0xffffffffu, mag_sq, s2);
    float mag = sqrtf(mag_sq) + 1e-11f;
    float a   = mag_sq / (1.f + mag_sq);
    float v   = acc * (a / mag);
    v_sm[bb*32 + j] = v;

    if (mode == 2) {
        out[(b*32 + o)*32 + j] = v;
        if (j == 0) out[32768 + b*32 + o] = a;
    } else {
        __syncthreads();
        float4 vq[8];
        const float4* vv4 = (const float4*)(v_sm + bb*32);
        #pragma unroll
        for (int q = 0; q < 8; ++q) vq[q] = vv4[q];
        float* zb = g_z + (b*32 + o)*512;
        #pragma unroll
        for (int k = 0; k < 16; ++k) {
            int ci = j + k*32;
            const float4* wr = (const float4*)(W_sm + ci*36);
            float za = 0.f;
            #pragma unroll
            for (int q = 0; q < 8; ++q) {
                float4 w4 = wr[q];
                za += w4.x*vq[q].x + w4.y*vq[q].y + w4.z*vq[q].z + w4.w*vq[q].w;
            }
            if (mode == 1) za += zb[ci];   // accumulate z_cum
            zb[ci] = za;
        }
    }
}

// ---------------------------------------------------------------------------
extern "C" void kernel_launch(void* const* d_in, const int* in_sizes, int n_in,
                              void* d_out, int out_size)
{
    const float* x = (const float*)d_in[0];
    const float* W = (const float*)(n_in > 1 ? d_in[1] : d_in[0]);
    for (int i = 0; i < n_in; ++i) {
        if (in_sizes[i] == 32*128*16*32)      x = (const float*)d_in[i];
        else if (in_sizes[i] == 16*32*32*32)  W = (const float*)d_in[i];
    }
    float* out = (float*)d_out;

    cudaFuncSetAttribute(k_s, cudaFuncAttributeMaxDynamicSharedMemorySize, SMEM_S);

    k_y0<<<256, 512>>>(x);
    k_s <<<128, 256, SMEM_S>>>(W, 0, nullptr);   // v0, z_cum = z0
    k_f <<<512, 256>>>(x, /*use_toff=*/0, /*write_mp=*/1);  // y1, S, max partials
    k_s <<<128, 256, SMEM_S>>>(W, 1, nullptr);   // v1, z_cum += z1, g_t
    k_f <<<512, 256>>>(x, 1, 0);                 // y2, S
    k_s <<<128, 256, SMEM_S>>>(W, 2, out);       // v2, a2 -> out
}

// round 7
// speedup vs baseline: 1.2166x; 1.0044x over previous
#include <cuda_runtime.h>

// Shapes: B=32, N=128, IN_CH=16, IN_DIM=32, OUT_CH=32, OUT_DIM=32, P=2048
// x[b,n,c,i]  : b*65536 + n*512 + c*32 + i
// W[c,o,i,j]  : c*32768 + o*1024 + i*32 + j
// y/z[b,o,c,i]: (b*32+o)*512 + c*32 + i
//
// b_ij is linear in the z-history: b_t = x · (z_0+..+z_{t-1}); never materialized.

typedef unsigned long long u64;

__device__ __forceinline__ u64 pk(float a, float b) {
    u64 r; asm("mov.b64 %0,{%1,%2};" : "=l"(r) : "f"(a), "f"(b)); return r;
}
__device__ __forceinline__ void upk(u64 p, float& a, float& b) {
    asm("mov.b64 {%0,%1},%2;" : "=f"(a), "=f"(b) : "l"(p));
}
__device__ __forceinline__ void fma2(u64& d, u64 a, u64 b) {
    asm("fma.rn.f32x2 %0,%1,%2,%0;" : "+l"(d) : "l"(a), "l"(b));
}

__device__ float g_y  [32*32*16*32]; // unnormalized y[b,o,c,i]
__device__ float g_y0p[32*8*512];    // iter-0 partial means
__device__ float g_z  [32*32*16*32]; // cumulative z
__device__ float g_sp [32*16*32];    // partial weight sums [b][c][o]
__device__ float g_mp [32*16*32];    // partial b-max       [b][c][o]
__device__ float g_t  [32*32];       // softmax offset per (b,o)

// ---------------------------------------------------------------------------
__global__ void k_y0(const float* __restrict__ x)
{
    int b = blockIdx.x >> 3, k = blockIdx.x & 7, t = threadIdx.x;
    const float* xb = x + b*65536 + k*16*512 + t;
    float acc = 0.f;
    #pragma unroll
    for (int n = 0; n < 16; ++n) acc += xb[n*512];
    g_y0p[b*4096 + k*512 + t] = acc * (1.f/2048.f);
}

// ---------------------------------------------------------------------------
// k_f: fused routing step per (b,c) tile. grid 512, 256 threads.
// ---------------------------------------------------------------------------
__global__ void k_f(const float* __restrict__ x, int use_toff, int write_mp)
{
    __shared__ float x_sm[128*32];
    __shared__ float w_sm[128*36];
    __shared__ float mred[8*33];
    __shared__ float sred[8*33];
    __shared__ float toff_sm[32];
    int b = blockIdx.x >> 4, c = blockIdx.x & 15;
    int t = threadIdx.x, lane = t & 31, grp = t >> 5;

    const float* xb = x + b*65536 + c*32;
    #pragma unroll
    for (int nn = 0; nn < 16; ++nn) {
        int n = nn*8 + grp;
        x_sm[n*32 + lane] = xb[n*512 + lane];
    }
    if (t < 32) toff_sm[t] = use_toff ? g_t[b*32 + t] : 0.f;

    // z_cum row for o = lane as 16 packed f32x2 (register-resident)
    u64 zr[16];
    const ulonglong2* zg = (const ulonglong2*)(g_z + (b*32 + lane)*512 + c*32);
    #pragma unroll
    for (int q = 0; q < 8; ++q) { ulonglong2 v = zg[q]; zr[2*q] = v.x; zr[2*q+1] = v.y; }
    __syncthreads();

    float toff = toff_sm[lane];
    float bmax = -1e30f, ssum = 0.f;
    #pragma unroll 2
    for (int nn = 0; nn < 16; ++nn) {
        int n = grp*16 + nn;
        const ulonglong2* xr = (const ulonglong2*)(x_sm + n*32);
        u64 a0 = 0, a1 = 0;
        #pragma unroll
        for (int q = 0; q < 8; ++q) {
            ulonglong2 xv = xr[q];
            fma2(a0, xv.x, zr[2*q]);
            fma2(a1, xv.y, zr[2*q+1]);
        }
        float l0,h0,l1,h1; upk(a0,l0,h0); upk(a1,l1,h1);
        float du = (l0+h0)+(l1+h1);
        bmax = fmaxf(bmax, du);
        float w = __expf(du - toff);
        ssum += w;
        w_sm[n*36 + lane] = w;
    }
    mred[grp*33 + lane] = bmax;
    sred[grp*33 + lane] = ssum;
    __syncthreads();
    if (t < 32) {
        float m = -1e30f, s = 0.f;
        #pragma unroll
        for (int g = 0; g < 8; ++g) {
            m = fmaxf(m, mred[g*33 + t]);
            s += sred[g*33 + t];
        }
        if (write_mp) g_mp[b*512 + c*32 + t] = m;
        g_sp[b*512 + c*32 + t] = s;
    }

    // phase2: thread (i=lane, o in [o0,o0+4)); packed over o-pairs
    u64 acc01 = 0, acc23 = 0;
    int o0 = grp*4;
    #pragma unroll 4
    for (int n = 0; n < 128; ++n) {
        float xv = x_sm[n*32 + lane];
        ulonglong2 wv = *(const ulonglong2*)(w_sm + n*36 + o0);  // 16B-aligned
        u64 xs = pk(xv, xv);
        fma2(acc01, wv.x, xs);
        fma2(acc23, wv.y, xs);
    }
    float a0,a1,a2,a3; upk(acc01,a0,a1); upk(acc23,a2,a3);
    float* yb = g_y + b*16384 + c*32 + lane;
    yb[(o0+0)*512] = a0; yb[(o0+1)*512] = a1;
    yb[(o0+2)*512] = a2; yb[(o0+3)*512] = a3;
}

// ---------------------------------------------------------------------------
// k_s: s[b,o,j] = (1/S) sum_ci y[b,o,ci] W[ci,o,j]; squash -> v,a;
//      z_cum[b,o,ci] (+)= sum_j W[ci,o,j] v[b,o,j]
// grid 256 (o | b-group of 4), 256 threads.
// W held in ci-pair layout: W2[ci>>1][j][ci&1], row stride 66 words
//   -> s-loop: LDS.64 pair + FFMA2, conflict-free
//   -> z-loop: register-blocked FFMA2, packed outputs
// ---------------------------------------------------------------------------
#define SMEM_S (19456*4)
__global__ void k_s(const float* __restrict__ Wg, int mode, float* __restrict__ out)
{
    extern __shared__ float sm[];
    float* W2   = sm;                  // [256][66]
    float* y_sm = sm + 16896;          // [4][512]
    float* part = sm + 18944;          // [128]
    float* v_sm = sm + 19072;          // [4][32]
    u64*   v2   = (u64*)(sm + 19200);  // [4][32] packed (v,v)

    int o  = blockIdx.x & 31;
    int b0 = (blockIdx.x >> 5) * 4;
    int t  = threadIdx.x;

    // W slice for this o -> pair layout
    const float4* W4 = (const float4*)Wg;
    #pragma unroll
    for (int c = 0; c < 16; ++c) {
        float4 w = W4[c*8192 + o*256 + t];
        int i = t >> 3, j0 = (t & 7) * 4;
        float* dst = W2 + (c*16 + (i >> 1))*66 + j0*2 + (i & 1);
        dst[0] = w.x; dst[2] = w.y; dst[4] = w.z; dst[6] = w.w;
    }
    if (mode == 0) {
        #pragma unroll
        for (int q = 0; q < 8; ++q) {
            int idx = q*256 + t, bb = idx >> 9, ci = idx & 511;
            float acc = 0.f;
            #pragma unroll
            for (int k = 0; k < 8; ++k) acc += g_y0p[(b0+bb)*4096 + k*512 + ci];
            y_sm[bb*512 + ci] = acc;
        }
    } else {
        #pragma unroll
        for (int q = 0; q < 8; ++q) {
            int idx = q*256 + t, bb = idx >> 9, ci = idx & 511;
            y_sm[bb*512 + ci] = g_y[(b0+bb)*16384 + o*512 + ci];
        }
    }
    __syncthreads();

    int j = t & 31, half = (t >> 5) & 1, bb = t >> 6, b = b0 + bb;

    // s partial over this thread's half of the ci range
    u64 pa0 = 0, pa1 = 0;
    {
        const ulonglong2* y4 = (const ulonglong2*)(y_sm + bb*512 + half*256);
        const float* wbase = W2 + (half*128)*66 + 2*j;
        #pragma unroll 4
        for (int q = 0; q < 64; ++q) {
            ulonglong2 yv = y4[q];
            u64 w0 = *(const u64*)(wbase + (q*2  )*66);
            u64 w1 = *(const u64*)(wbase + (q*2+1)*66);
            fma2(pa0, yv.x, w0);
            fma2(pa1, yv.y, w1);
        }
    }
    float l0,h0,l1,h1; upk(pa0,l0,h0); upk(pa1,l1,h1);
    float sacc = (l0+h0)+(l1+h1);
    if (half == 1) part[bb*32 + j] = sacc;
    __syncthreads();
    if (half == 0) {
        sacc += part[bb*32 + j];
        float Sinv = 1.f;
        if (mode != 0) {
            float sv = (j < 16) ? g_sp[b*512 + j*32 + o] : 0.f;
            #pragma unroll
            for (int s2 = 16; s2; s2 >>= 1) sv += __shfl_xor_sync(0xffffffffu, sv, s2);
            Sinv = 1.f / sv;
            if (mode == 1) {
                float mv = (j < 16) ? g_mp[b*512 + j*32 + o] : -1e30f;
                #pragma unroll
                for (int s2 = 16; s2; s2 >>= 1)
                    mv = fmaxf(mv, __shfl_xor_sync(0xffffffffu, mv, s2));
                if (j == 0) g_t[b*32 + o] = mv;
            }
        }
        float acc = sacc * Sinv;
        float mag_sq = acc*acc;
        #pragma unroll
        for (int s2 = 16; s2; s2 >>= 1) mag_sq += __shfl_xor_sync(0xffffffffu, mag_sq, s2);
        float mag = sqrtf(mag_sq) + 1e-11f;
        float a   = mag_sq / (1.f + mag_sq);
        float v   = acc * (a / mag);
        v_sm[bb*32 + j] = v;
        v2[bb*32 + j]   = pk(v, v);
        if (mode == 2) {
            out[(b*32 + o)*32 + j] = v;
            if (j == 0) out[32768 + b*32 + o] = a;
        }
    }
    if (mode == 2) return;
    __syncthreads();

    // z: thread owns ci pair (2t, 2t+1) for 4 b's; packed FFMA2 throughout
    u64 zacc[4] = {0,0,0,0};
    const u64* wr = (const u64*)(W2 + t*66);
    #pragma unroll
    for (int h = 0; h < 2; ++h) {
        u64 wreg[16];
        #pragma unroll
        for (int q = 0; q < 16; ++q) wreg[q] = wr[h*16 + q];
        #pragma unroll
        for (int bq = 0; bq < 4; ++bq) {
            const u64* vv = v2 + bq*32 + h*16;
            #pragma unroll
            for (int q = 0; q < 16; ++q) fma2(zacc[bq], wreg[q], vv[q]);
        }
    }
    #pragma unroll
    for (int bq = 0; bq < 4; ++bq) {
        float zl, zh; upk(zacc[bq], zl, zh);
        float2* zp = (float2*)(g_z + ((b0+bq)*32 + o)*512) + t;
        if (mode == 1) { float2 old = *zp; zl += old.x; zh += old.y; }
        *zp = make_float2(zl, zh);
    }
}

// ---------------------------------------------------------------------------
extern "C" void kernel_launch(void* const* d_in, const int* in_sizes, int n_in,
                              void* d_out, int out_size)
{
    const float* x = (const float*)d_in[0];
    const float* W = (const float*)(n_in > 1 ? d_in[1] : d_in[0]);
    for (int i = 0; i < n_in; ++i) {
        if (in_sizes[i] == 32*128*16*32)      x = (const float*)d_in[i];
        else if (in_sizes[i] == 16*32*32*32)  W = (const float*)d_in[i];
    }
    float* out = (float*)d_out;

    cudaFuncSetAttribute(k_s, cudaFuncAttributeMaxDynamicSharedMemorySize, SMEM_S);

    k_y0<<<256, 512>>>(x);
    k_s <<<256, 256, SMEM_S>>>(W, 0, nullptr);   // v0, z_cum = z0
    k_f <<<512, 256>>>(x, 0, 1);                 // y1, S + max partials
    k_s <<<256, 256, SMEM_S>>>(W, 1, nullptr);   // v1, z_cum += z1, g_t
    k_f <<<512, 256>>>(x, 1, 0);                 // y2, S
    k_s <<<256, 256, SMEM_S>>>(W, 2, out);       // v2, a2 -> out
}

// round 9
// speedup vs baseline: 1.2243x; 1.0063x over previous
#include <cuda_runtime.h>

// Shapes: B=32, N=128, IN_CH=16, IN_DIM=32, OUT_CH=32, OUT_DIM=32, P=2048
// x[b,n,c,i]  : b*65536 + n*512 + c*32 + i
// W[c,o,i,j]  : c*32768 + o*1024 + i*32 + j
// y/z[b,o,c,i]: (b*32+o)*512 + c*32 + i
// b_ij is linear in the z-history: b_t = x · (z_0+..+z_{t-1}); never materialized.

typedef unsigned long long u64;

__device__ __forceinline__ u64 pk(float a, float b) {
    u64 r; asm("mov.b64 %0,{%1,%2};" : "=l"(r) : "f"(a), "f"(b)); return r;
}
__device__ __forceinline__ void upk(u64 p, float& a, float& b) {
    asm("mov.b64 {%0,%1},%2;" : "=f"(a), "=f"(b) : "l"(p));
}
__device__ __forceinline__ void fma2(u64& d, u64 a, u64 b) {
    asm("fma.rn.f32x2 %0,%1,%2,%0;" : "+l"(d) : "l"(a), "l"(b));
}

__device__ __align__(16) float g_y  [32*32*16*32];
__device__ __align__(16) float g_y0p[32*8*512];
__device__ __align__(16) float g_z  [32*32*16*32];
__device__ float g_sp [32*16*32];
__device__ float g_mp [32*16*32];
__device__ float g_t  [32*32];

// ---------------------------------------------------------------------------
__global__ void k_y0(const float* __restrict__ x)
{
    int b = blockIdx.x >> 3, k = blockIdx.x & 7, t = threadIdx.x;
    const float* xb = x + b*65536 + k*16*512 + t;
    float acc = 0.f;
    #pragma unroll
    for (int n = 0; n < 16; ++n) acc += xb[n*512];
    g_y0p[b*4096 + k*512 + t] = acc * (1.f/2048.f);
}

// ---------------------------------------------------------------------------
// k_f: fused routing step per (b,c) tile. grid 512, 512 threads (16 warps).
// ---------------------------------------------------------------------------
__global__ __launch_bounds__(512) void k_f(const float* __restrict__ x,
                                           int use_toff, int write_mp)
{
    __shared__ __align__(16) float x_sm[128*32];   // [n][i]
    __shared__ __align__(16) float w_sm[128*36];   // [n][o] padded
    __shared__ __align__(16) float z_sm[32*34];    // [o][i] padded (staged once)
    __shared__ float mred[16*33];
    __shared__ float sred[16*33];
    __shared__ float toff_sm[32];
    int b = blockIdx.x >> 4, c = blockIdx.x & 15;
    int t = threadIdx.x, lane = t & 31, wid = t >> 5;

    const float* xb = x + b*65536 + c*32;
    #pragma unroll
    for (int nn = 0; nn < 8; ++nn) {
        int n = wid*8 + nn;
        x_sm[n*32 + lane] = xb[n*512 + lane];
    }
    {   // z slice: 1024 floats, coalesced, staged once for the whole block
        int o = t >> 4, i2 = t & 15;
        float2 vv = *(const float2*)(g_z + (b*32 + o)*512 + c*32 + 2*i2);
        *(float2*)(z_sm + o*34 + 2*i2) = vv;
    }
    if (t < 32) toff_sm[t] = use_toff ? g_t[b*32 + t] : 0.f;
    __syncthreads();

    // z row for o = lane, packed into registers (LDS.64, once)
    u64 zr[16];
    #pragma unroll
    for (int q = 0; q < 16; ++q) zr[q] = *(const u64*)(z_sm + lane*34 + 2*q);

    float toff = toff_sm[lane];
    float bmax = -1e30f, ssum = 0.f;
    #pragma unroll
    for (int nn = 0; nn < 8; ++nn) {
        int n = wid*8 + nn;
        const ulonglong2* xr = (const ulonglong2*)(x_sm + n*32);  // broadcast
        u64 a0 = 0, a1 = 0;
        #pragma unroll
        for (int q = 0; q < 8; ++q) {
            ulonglong2 xv = xr[q];
            fma2(a0, xv.x, zr[2*q]);
            fma2(a1, xv.y, zr[2*q+1]);
        }
        float l0,h0,l1,h1; upk(a0,l0,h0); upk(a1,l1,h1);
        float du = (l0+h0)+(l1+h1);
        bmax = fmaxf(bmax, du);
        float w = __expf(du - toff);
        ssum += w;
        w_sm[n*36 + lane] = w;                         // stride-1: conflict-free
    }
    mred[wid*33 + lane] = bmax;
    sred[wid*33 + lane] = ssum;
    __syncthreads();
    if (t < 32) {
        float m = -1e30f, s = 0.f;
        #pragma unroll
        for (int g = 0; g < 16; ++g) {
            m = fmaxf(m, mred[g*33 + t]);
            s += sred[g*33 + t];
        }
        if (write_mp) g_mp[b*512 + c*32 + t] = m;
        g_sp[b*512 + c*32 + t] = s;
    }

    // phase2: warp owns o-pair o0 = wid*2; thread i = lane
    int o0 = wid*2;
    u64 acc0 = 0, acc1 = 0;
    #pragma unroll 4
    for (int n = 0; n < 128; n += 2) {
        float x0 = x_sm[n*32 + lane];                     // conflict-free
        float x1 = x_sm[(n+1)*32 + lane];
        u64 w0 = *(const u64*)(w_sm + n*36 + o0);         // broadcast LDS.64
        u64 w1 = *(const u64*)(w_sm + (n+1)*36 + o0);
        fma2(acc0, w0, pk(x0, x0));
        fma2(acc1, w1, pk(x1, x1));
    }
    float p0,p1,q0,q1; upk(acc0,p0,p1); upk(acc1,q0,q1);
    float* ybp = g_y + b*16384 + c*32 + lane;
    ybp[(o0  )*512] = p0 + q0;
    ybp[(o0+1)*512] = p1 + q1;
}

// ---------------------------------------------------------------------------
// k_s: s[b,o,j] = (1/S) sum_ci y[b,o,ci] W[ci,o,j]; squash -> v,a;
//      z_cum[b,o,ci] (+)= sum_j W[ci,o,j] v[b,o,j]
// grid 256 (o | b-group of 4), 512 threads (16 warps).
// W in ci-pair layout W2[ci>>1][j][ci&1] (row stride 66): LDS.64 + FFMA2.
// ---------------------------------------------------------------------------
#define SMEM_S (19584*4)
__global__ __launch_bounds__(512) void k_s(const float* __restrict__ Wg,
                                           int mode, float* __restrict__ out)
{
    extern __shared__ __align__(16) float sm[];
    float* W2   = sm;                  // [256][66]
    float* y_sm = sm + 16896;          // [4][512]
    float* part = sm + 18944;          // [3][4][32]
    u64*   v2   = (u64*)(sm + 19328);  // [4][32] packed (v,v)

    int o  = blockIdx.x & 31;
    int b0 = (blockIdx.x >> 5) * 4;
    int t  = threadIdx.x;

    // W slice for this o -> pair layout
    const float4* W4 = (const float4*)Wg;
    #pragma unroll
    for (int k = 0; k < 8; ++k) {
        int gi = k*512 + t;
        int c = gi >> 8, tt = gi & 255;
        float4 w = W4[c*8192 + o*256 + tt];
        int i = tt >> 3, j0 = (tt & 7) * 4;
        float* dst = W2 + (c*16 + (i >> 1))*66 + j0*2 + (i & 1);
        dst[0] = w.x; dst[2] = w.y; dst[4] = w.z; dst[6] = w.w;
    }
    {
        int bb = t >> 7, ci4 = t & 127;
        if (mode == 0) {
            const float4* yp = (const float4*)g_y0p + (b0+bb)*1024 + ci4;
            float4 acc = yp[0];
            #pragma unroll
            for (int k = 1; k < 8; ++k) {
                float4 v = yp[k*128];
                acc.x += v.x; acc.y += v.y; acc.z += v.z; acc.w += v.w;
            }
            ((float4*)y_sm)[t] = acc;
        } else {
            ((float4*)y_sm)[t] =
                ((const float4*)(g_y + (b0+bb)*16384 + o*512))[ci4];
        }
    }
    __syncthreads();

    int j = t & 31, wid = t >> 5;
    int quarter = wid & 3, bb = wid >> 2, b = b0 + bb;

    // s partial over this warp's quarter of the ci range (128 ci = 64 pairs)
    u64 pa0 = 0, pa1 = 0;
    {
        const ulonglong2* y4 = (const ulonglong2*)(y_sm + bb*512 + quarter*128);
        const float* wbase = W2 + (quarter*64)*66 + 2*j;
        #pragma unroll 4
        for (int q = 0; q < 32; ++q) {
            ulonglong2 yv = y4[q];                         // broadcast
            u64 w0 = *(const u64*)(wbase + (q*2  )*66);
            u64 w1 = *(const u64*)(wbase + (q*2+1)*66);
            fma2(pa0, yv.x, w0);
            fma2(pa1, yv.y, w1);
        }
    }
    float l0,h0,l1,h1; upk(pa0,l0,h0); upk(pa1,l1,h1);
    float sacc = (l0+h0)+(l1+h1);
    if (quarter) part[((quarter-1)*4 + bb)*32 + j] = sacc;
    __syncthreads();
    if (quarter == 0) {
        sacc += part[bb*32+j] + part[(4+bb)*32+j] + part[(8+bb)*32+j];
        float Sinv = 1.f;
        if (mode != 0) {
            float sv = (j < 16) ? g_sp[b*512 + j*32 + o] : 0.f;
            #pragma unroll
            for (int s2 = 16; s2; s2 >>= 1) sv += __shfl_xor_sync(0xffffffffu, sv, s2);
            Sinv = 1.f / sv;
            if (mode == 1) {
                float mv = (j < 16) ? g_mp[b*512 + j*32 + o] : -1e30f;
                #pragma unroll
                for (int s2 = 16; s2; s2 >>= 1)
                    mv = fmaxf(mv, __shfl_xor_sync(0xffffffffu, mv, s2));
                if (j == 0) g_t[b*32 + o] = mv;
            }
        }
        float acc = sacc * Sinv;
        float mag_sq = acc*acc;
        #pragma unroll
        for (int s2 = 16; s2; s2 >>= 1) mag_sq += __shfl_xor_sync(0xffffffffu, mag_sq, s2);
        float mag = sqrtf(mag_sq) + 1e-11f;
        float a   = mag_sq / (1.f + mag_sq);
        float v   = acc * (a / mag);
        v2[bb*32 + j] = pk(v, v);
        if (mode == 2) {
            out[(b*32 + o)*32 + j] = v;
            if (j == 0) out[32768 + b*32 + o] = a;
        }
    }
    if (mode == 2) return;
    __syncthreads();

    // z: thread owns ci-pair p for 2 b's (512 threads cover 256 pairs x 4 b)
    int p = t & 255, bh = t >> 8;
    u64 z0 = 0, z1 = 0;
    const u64* wr = (const u64*)(W2 + p*66);
    const u64* va = v2 + (bh*2    )*32;   // broadcast
    const u64* vb = v2 + (bh*2 + 1)*32;
    #pragma unroll
    for (int q = 0; q < 32; ++q) {
        u64 w = wr[q];
        fma2(z0, w, va[q]);
        fma2(z1, w, vb[q]);
    }
    {
        float zl, zh; upk(z0, zl, zh);
        float2* zp = (float2*)(g_z + ((b0 + bh*2)*32 + o)*512) + p;
        if (mode == 1) { float2 ov = *zp; zl += ov.x; zh += ov.y; }
        *zp = make_float2(zl, zh);
    }
    {
        float zl, zh; upk(z1, zl, zh);
        float2* zp = (float2*)(g_z + ((b0 + bh*2 + 1)*32 + o)*512) + p;
        if (mode == 1) { float2 ov = *zp; zl += ov.x; zh += ov.y; }
        *zp = make_float2(zl, zh);
    }
}

// ---------------------------------------------------------------------------
extern "C" void kernel_launch(void* const* d_in, const int* in_sizes, int n_in,
                              void* d_out, int out_size)
{
    const float* x = (const float*)d_in[0];
    const float* W = (const float*)(n_in > 1 ? d_in[1] : d_in[0]);
    for (int i = 0; i < n_in; ++i) {
        if (in_sizes[i] == 32*128*16*32)      x = (const float*)d_in[i];
        else if (in_sizes[i] == 16*32*32*32)  W = (const float*)d_in[i];
    }
    float* out = (float*)d_out;

    cudaFuncSetAttribute(k_s, cudaFuncAttributeMaxDynamicSharedMemorySize, SMEM_S);

    k_y0<<<256, 512>>>(x);
    k_s <<<256, 512, SMEM_S>>>(W, 0, nullptr);   // v0, z_cum = z0
    k_f <<<512, 512>>>(x, 0, 1);                 // y1, S + max partials
    k_s <<<256, 512, SMEM_S>>>(W, 1, nullptr);   // v1, z_cum += z1, g_t
    k_f <<<512, 512>>>(x, 1, 0);                 // y2, S
    k_s <<<256, 512, SMEM_S>>>(W, 2, out);       // v2, a2 -> out
}